// round 7
// baseline (speedup 1.0000x reference)
#include <cuda_runtime.h>
#include <math.h>

#define C 150
#define NBKT (2*C)                // 300 buckets
#define D 128
#define NCHUNK 18
#define NSLICE 8
#define GRID1 (NSLICE * NCHUNK)   // 144 CTAs = one clean wave on 148 SMs
#define COLS 16                   // columns per CTA slice
#define NB0 304                   // K0 blocks
#define SKIPC 0xFFFFu
#define DUPF  0x8000u
#define NMAX 2097152
#define WACC_F (NBKT*COLS)        // 4800 floats per-warp accumulator
#define LISTCAP 2048              // per-warp dup list capacity (expected ~330)
#define INV_TEMP 5.0f

// ---- device scratch (fully re-written every launch) ----
__device__ unsigned g_codesw[NMAX / 2];             // packed u16 bucket codes
__device__ int      g_cntpart[NB0 * NBKT];          // per-K0-block integer histograms
__device__ float    g_part1[GRID1 * WACC_F];        // per-CTA partial sums
__device__ float    g_ab[2 * C * D];                // normalized means (A then B)
__device__ float    g_contrib[C];                   // per-class symmetric-NCE contribution

// ---------------------------------------------------------------------------
// K0: octant-based encode. Computes u16 bucket codes, flags any point whose
// bucket duplicates another point's bucket WITHIN its aligned 8-point octant
// (DUPF bit), and builds deterministic integer count histograms.
// ---------------------------------------------------------------------------
__global__ __launch_bounds__(256)
void k0_encode(const int* __restrict__ mask, const int* __restrict__ seg,
               const int* __restrict__ grp, int N, int NPAD)
{
    __shared__ int hist[NBKT];
    for (int i = threadIdx.x; i < NBKT; i += 256) hist[i] = 0;
    __syncthreads();

    const int octs = NPAD >> 3;
    for (int oc = blockIdx.x * 256 + threadIdx.x; oc < octs; oc += NB0 * 256) {
        const int i0 = oc * 8;
        unsigned c[8];
        if (i0 + 8 <= N) {
            int4 m0 = *(const int4*)(mask + i0), m1 = *(const int4*)(mask + i0 + 4);
            int4 s0 = *(const int4*)(seg  + i0), s1 = *(const int4*)(seg  + i0 + 4);
            int4 g0 = *(const int4*)(grp  + i0), g1 = *(const int4*)(grp  + i0 + 4);
            int mm[8] = {m0.x,m0.y,m0.z,m0.w,m1.x,m1.y,m1.z,m1.w};
            int ss[8] = {s0.x,s0.y,s0.z,s0.w,s1.x,s1.y,s1.z,s1.w};
            int gg[8] = {g0.x,g0.y,g0.z,g0.w,g1.x,g1.y,g1.z,g1.w};
            #pragma unroll
            for (int k = 0; k < 8; k++)
                c[k] = (mm[k] > 0 && ss[k] != -1 && (unsigned)gg[k] <= 1u)
                     ? (unsigned)gg[k] * C + (unsigned)min(max(ss[k], 0), C - 1)
                     : SKIPC;
        } else {
            #pragma unroll
            for (int k = 0; k < 8; k++) {
                const int idx = i0 + k;
                c[k] = SKIPC;
                if (idx < N) {
                    int m = mask[idx], s = seg[idx], g = grp[idx];
                    if (m > 0 && s != -1 && (unsigned)g <= 1u)
                        c[k] = (unsigned)g * C + (unsigned)min(max(s, 0), C - 1);
                }
            }
        }
        // histogram (counts include soon-to-be-flagged points)
        #pragma unroll
        for (int k = 0; k < 8; k++)
            if (c[k] < NBKT) atomicAdd(&hist[c[k]], 1);
        // intra-octant duplicate detection
        unsigned f = 0;
        #pragma unroll
        for (int i = 0; i < 8; i++)
            #pragma unroll
            for (int j = i + 1; j < 8; j++)
                if (c[i] < NBKT && c[i] == c[j]) f |= (1u << i) | (1u << j);
        #pragma unroll
        for (int k = 0; k < 8; k++)
            if ((f >> k) & 1u) c[k] |= DUPF;

        uint4 w;
        w.x = c[0] | (c[1] << 16);
        w.y = c[2] | (c[3] << 16);
        w.z = c[4] | (c[5] << 16);
        w.w = c[6] | (c[7] << 16);
        ((uint4*)g_codesw)[oc] = w;
    }
    __syncthreads();
    for (int i = threadIdx.x; i < NBKT; i += 256)
        g_cntpart[blockIdx.x * NBKT + i] = hist[i];
}

// ---------------------------------------------------------------------------
// K1: column-sliced segmented sums, octant steps.
// Per step a warp covers 8 points x 16 cols: 1 LDG.128 + 1 SHFL (code word)
// + 1 predicated LDS.128/FADDx4/STS.128. K0's DUPF flags guarantee the 8
// simultaneous bucket rows are distinct -> race-free with ZERO collision
// logic in the hot loop. Flagged points drained afterwards from a compacted
// per-warp list (deterministic order, prefetched).
// ---------------------------------------------------------------------------
__global__ __launch_bounds__(256, 1)
void k1_accumulate(const float* __restrict__ pred, int N, int chTiles)
{
    extern __shared__ float sm[];
    const int tid  = threadIdx.x;
    const int wid  = tid >> 5;
    const int lane = tid & 31;
    const int o    = lane >> 2;      // octant point 0..7
    const int q4   = lane & 3;       // float4 index within 16 cols
    const int srcw = o >> 1;         // code-word sub-index for this point
    const int oh   = o & 1;          // which half of the code word

    float*    wacc  = sm + wid * WACC_F;
    unsigned* wlist = (unsigned*)(sm + 8 * WACC_F) + wid * LISTCAP;

    for (int i = tid; i < 8 * WACC_F; i += 256) sm[i] = 0.0f;
    __syncthreads();

    const int slice   = blockIdx.x / NCHUNK;
    const int chunk   = blockIdx.x % NCHUNK;
    const int colbase = slice * COLS;

    auto loadtile = [&](int tt, float4* v, unsigned& ck) {
        const int base = (chunk * chTiles + tt) * 64;
        ck = g_codesw[(base >> 1) + lane];           // 32 words = 64 codes
        if (base + 64 <= N) {
            const float4* p = (const float4*)(pred + (size_t)(base + o) * D + colbase) + q4;
            #pragma unroll
            for (int u = 0; u < 8; u++) v[u] = p[(size_t)u * 256];  // 8 pts * 128 floats
        } else {
            #pragma unroll
            for (int u = 0; u < 8; u++) {
                int idx = base + 8 * u + o;
                idx = idx < N ? idx : N - 1;         // clamp; code is SKIPC for OOB
                v[u] = ((const float4*)(pred + (size_t)idx * D + colbase))[q4];
            }
        }
    };

    auto accum = [&](const float4* v, unsigned ck) {
        #pragma unroll
        for (int u = 0; u < 8; u++) {
            const unsigned pp = __shfl_sync(0xffffffffu, ck, 4 * u + srcw);
            const unsigned co = oh ? (pp >> 16) : (pp & 0xffffu);
            if (co < NBKT) {                          // distinct rows guaranteed
                float4* cell = (float4*)(wacc + co * COLS) + q4;
                float4 a = *cell;
                a.x += v[u].x; a.y += v[u].y; a.z += v[u].z; a.w += v[u].w;
                *cell = a;
            }
        }
    };

    float4 va[8], vb[8];
    unsigned cka, ckb;
    int t = wid;
    if (t < chTiles) {
        loadtile(t, va, cka);
        while (true) {
            int tn = t + 8;
            if (tn < chTiles) {
                loadtile(tn, vb, ckb);
                accum(va, cka);
                int tnn = tn + 8;
                if (tnn < chTiles) {
                    loadtile(tnn, va, cka);
                    accum(vb, ckb);
                    t = tnn;
                } else { accum(vb, ckb); break; }
            } else { accum(va, cka); break; }
        }
    }

    // ---- dup drain: compact flagged points of own tiles into list ----
    int cnt = 0;
    for (int tt = wid; tt < chTiles; tt += 8) {
        const int base = (chunk * chTiles + tt) * 64;
        const unsigned w = g_codesw[(base >> 1) + lane];   // L2-resident
        const unsigned lo = w & 0xffffu, hi = w >> 16;
        const bool f0 = (lo & DUPF) && (lo != SKIPC);
        const bool f1 = (hi & DUPF) && (hi != SKIPC);
        const unsigned b0 = __ballot_sync(0xffffffffu, f0);
        const unsigned b1 = __ballot_sync(0xffffffffu, f1);
        if (f0) {
            const int pos = cnt + __popc(b0 & ((1u << lane) - 1u));
            if (pos < LISTCAP)
                wlist[pos] = ((unsigned)(base + 2 * lane) << 9) | (lo & 0x1ffu);
        }
        cnt += __popc(b0);
        if (f1) {
            const int pos = cnt + __popc(b1 & ((1u << lane) - 1u));
            if (pos < LISTCAP)
                wlist[pos] = ((unsigned)(base + 2 * lane + 1) << 9) | (hi & 0x1ffu);
        }
        cnt += __popc(b1);
    }
    if (cnt > LISTCAP) cnt = LISTCAP;
    __syncwarp();

    // drain: 16 entries per batch (8 per half-warp pair slot), prefetched.
    const int hh = lane >> 4;        // entry slot parity within a pair-step
    const int cl = lane & 15;        // column
    for (int j = 0; j < cnt; j += 16) {
        unsigned e[8]; float v[8];
        #pragma unroll
        for (int k = 0; k < 8; k++) {
            const int idx = j + 2 * k + hh;
            e[k] = (idx < cnt) ? wlist[idx] : 0x1ffu;    // c=511 -> skipped
            v[k] = 0.0f;
            if (idx < cnt)
                v[k] = pred[(size_t)(e[k] >> 9) * D + colbase + cl];
        }
        #pragma unroll
        for (int k = 0; k < 8; k++) {
            const unsigned c  = e[k] & 0x1ffu;
            const unsigned c2 = __shfl_xor_sync(0xffffffffu, e[k], 16) & 0x1ffu;
            const float    vo = __shfl_xor_sync(0xffffffffu, v[k], 16);
            const bool   same = (c == c2);
            const float   val = same ? (v[k] + vo) : v[k];
            unsigned       cc = c;
            if (same && hh) cc = 0x1ffu;
            if (cc < NBKT) wacc[cc * COLS + cl] += val;
        }
    }
    __syncthreads();

    // reduce 8 warp slabs -> one CTA partial slab (deterministic order)
    for (int i = tid; i < WACC_F; i += 256) {
        float s = 0.0f;
        #pragma unroll
        for (int w = 0; w < 8; w++) s += sm[w * WACC_F + i];
        g_part1[(size_t)blockIdx.x * WACC_F + i] = s;
    }
}

// ---------------------------------------------------------------------------
// K2: reduce partials -> mean -> L2 normalize. grid = NBKT blocks, 128 threads.
// ---------------------------------------------------------------------------
__global__ void k2_mean_norm()
{
    __shared__ float red[D];
    const int gc = blockIdx.x;     // g*C + c
    const int d  = threadIdx.x;    // column 0..127

    float pc = 0.0f;
    for (int b = d; b < NB0; b += D) pc += (float)g_cntpart[b * NBKT + gc];
    red[d] = pc; __syncthreads();
    for (int s = 64; s > 0; s >>= 1) { if (d < s) red[d] += red[d + s]; __syncthreads(); }
    const float cnt = fmaxf(red[0], 1.0f);
    __syncthreads();

    const int cs = d >> 4, j = d & 15;   // slice, col-in-slice
    float s = 0.0f;
    #pragma unroll
    for (int h = 0; h < NCHUNK; h++)
        s += g_part1[(size_t)(cs * NCHUNK + h) * WACC_F + gc * COLS + j];
    const float mean = s / cnt;

    red[d] = mean * mean; __syncthreads();
    for (int s2 = 64; s2 > 0; s2 >>= 1) { if (d < s2) red[d] += red[d + s2]; __syncthreads(); }
    const float inv = rsqrtf(red[0]);

    g_ab[gc * D + d] = mean * inv;
}

// ---------------------------------------------------------------------------
// K3: block i computes logits row i AND column i in parallel groups of 256
// threads each, then both logsumexps. grid = C blocks, 512 threads.
// ---------------------------------------------------------------------------
__global__ __launch_bounds__(512)
void k3_lse()
{
    extern __shared__ float s3[];
    float* aT  = s3;                 // [D][152]
    float* bT  = aT + D * 152;       // [D][152]
    float* ai  = bT + D * 152;       // [D]
    float* bi  = ai + D;             // [D]
    float* red = bi + D;             // [2][256]
    __shared__ float diag_s, lse_s[2];

    const int i = blockIdx.x, tid = threadIdx.x;
    const int g2 = tid >> 8;         // 0: row group, 1: col group
    const int j  = tid & 255;

    for (int idx = tid; idx < C * D; idx += 512) {
        const int c = idx >> 7, d = idx & 127;
        aT[d * 152 + c] = g_ab[idx];
        bT[d * 152 + c] = g_ab[C * D + idx];
    }
    if (tid < D)            ai[tid] = g_ab[i * D + tid];
    else if (tid < 2 * D)   bi[tid - D] = g_ab[C * D + i * D + (tid - D)];
    __syncthreads();

    float x = -1e30f;
    if (j < C) {
        const float* vec = g2 ? bi : ai;
        const float* mat = g2 ? aT : bT;
        float xs = 0.0f;
        #pragma unroll 8
        for (int k = 0; k < D; k++) xs += vec[k] * mat[k * 152 + j];
        x = xs * INV_TEMP;
        if (g2 == 0 && j == i) diag_s = x;
    }

    red[tid] = x; __syncthreads();
    for (int s = 128; s > 0; s >>= 1) {
        if (j < s) red[tid] = fmaxf(red[tid], red[tid + s]);
        __syncthreads();
    }
    const float mx = red[g2 << 8]; __syncthreads();
    red[tid] = (j < C) ? expf(x - mx) : 0.0f; __syncthreads();
    for (int s = 128; s > 0; s >>= 1) {
        if (j < s) red[tid] += red[tid + s];
        __syncthreads();
    }
    if (j == 0) lse_s[g2] = mx + logf(red[g2 << 8]);
    __syncthreads();

    if (tid == 0) g_contrib[i] = lse_s[0] + lse_s[1] - 2.0f * diag_s;
}

// ---------------------------------------------------------------------------
// K4: final scalar. 1 block, 256 threads.
// ---------------------------------------------------------------------------
__global__ void k4_final(float* __restrict__ out)
{
    __shared__ float red[256];
    const int tid = threadIdx.x;
    red[tid] = (tid < C) ? g_contrib[tid] : 0.0f; __syncthreads();
    for (int s = 128; s > 0; s >>= 1) { if (tid < s) red[tid] += red[tid + s]; __syncthreads(); }
    if (tid == 0) out[0] = red[0] * (1.0f / (2.0f * C));
}

// ---------------------------------------------------------------------------
extern "C" void kernel_launch(void* const* d_in, const int* in_sizes, int n_in,
                              void* d_out, int out_size)
{
    const float* pred = (const float*)d_in[0];
    // d_in[1] = target (unused by the loss math)
    const int* mask = (const int*)d_in[2];
    const int* seg  = (const int*)d_in[3];
    const int* grp  = (const int*)d_in[4];
    const int N = in_sizes[2];

    const int totTiles = (N + 63) / 64;
    const int chTiles  = (totTiles + NCHUNK - 1) / NCHUNK;
    const int NPAD     = NCHUNK * chTiles * 64;   // <= NMAX for N <= ~2.09M

    const size_t smem1 = (8 * WACC_F + 8 * LISTCAP) * sizeof(float);  // 153.6K + 64K = 217.6KB
    cudaFuncSetAttribute(k1_accumulate, cudaFuncAttributeMaxDynamicSharedMemorySize, (int)smem1);
    const size_t smem3 = (2 * D * 152 + 2 * D + 512) * sizeof(float);
    cudaFuncSetAttribute(k3_lse, cudaFuncAttributeMaxDynamicSharedMemorySize, (int)smem3);

    k0_encode<<<NB0, 256>>>(mask, seg, grp, N, NPAD);
    k1_accumulate<<<GRID1, 256, smem1>>>(pred, N, chTiles);
    k2_mean_norm<<<NBKT, D>>>();
    k3_lse<<<C, 512, smem3>>>();
    k4_final<<<1, 256>>>((float*)d_out);
}

// round 8
// speedup vs baseline: 1.2190x; 1.2190x over previous
#include <cuda_runtime.h>
#include <math.h>

#define C 150
#define NBKT 300
#define D 128
#define GRID1 144
#define NMAX 2097152
#define TS 512                      // points per sort tile (one warp)
#define TMAX (NMAX / TS)            // 4096
#define INVC 511u
#define INV_TEMP 5.0f

// ---- device scratch (fully re-written every launch) ----
__device__ unsigned short g_codes[NMAX];
__device__ int      g_thist[TMAX * NBKT];      // per-tile histograms [t][b]
__device__ int      g_toffs[TMAX * NBKT];      // exclusive tile prefix [t][b]
__device__ int      g_total[NBKT];
__device__ int      g_base[NBKT];
__device__ int      g_M[1];
__device__ unsigned g_sorted[NMAX];            // (idx<<9)|bucket, stable-sorted
__device__ float    g_part1[GRID1 * NBKT * D]; // per-CTA partial slabs
__device__ float    g_ab[NBKT * D];            // normalized means
__device__ float    g_contrib[C];

// ---------------------------------------------------------------------------
// K0: encode codes + per-tile histograms (warp-private, match_any -> stable).
// ---------------------------------------------------------------------------
__global__ __launch_bounds__(256)
void k0_encode(const int* __restrict__ mask, const int* __restrict__ seg,
               const int* __restrict__ grp, int N, int T)
{
    __shared__ int shist[8][NBKT];
    const int wid = threadIdx.x >> 5, lane = threadIdx.x & 31;
    const int t = blockIdx.x * 8 + wid;
    if (t >= T) return;
    int* hist = shist[wid];
    for (int b = lane; b < NBKT; b += 32) hist[b] = 0;
    __syncwarp();

    const int p0 = t * TS;
    for (int s = 0; s < TS; s += 32) {
        const int idx = p0 + s + lane;
        unsigned c = INVC;
        if (idx < N) {
            const int m = mask[idx], sv = seg[idx], g = grp[idx];
            if (m > 0 && sv != -1 && (unsigned)g <= 1u)
                c = (unsigned)g * C + (unsigned)min(max(sv, 0), C - 1);
        }
        g_codes[idx] = (unsigned short)c;      // idx < T*TS <= NMAX always
        const unsigned mm = __match_any_sync(0xffffffffu, c);
        const int leader = __ffs(mm) - 1;
        if (lane == leader && c < NBKT) hist[c] += __popc(mm);
        __syncwarp();
    }
    for (int b = lane; b < NBKT; b += 32)
        g_thist[t * NBKT + b] = hist[b];
}

// ---------------------------------------------------------------------------
// ScanA: per bucket b, exclusive prefix of g_thist over tiles; also totals.
// ---------------------------------------------------------------------------
__global__ __launch_bounds__(256)
void k_scanA(int T)
{
    __shared__ int sred[256];
    const int b = blockIdx.x, tid = threadIdx.x;
    const int per = (T + 255) / 256;
    const int t0 = tid * per;

    int lsum = 0;
    for (int i = 0; i < per; i++) {
        const int t = t0 + i;
        if (t < T) lsum += g_thist[t * NBKT + b];
    }
    sred[tid] = lsum; __syncthreads();
    for (int off = 1; off < 256; off <<= 1) {
        const int v = (tid >= off) ? sred[tid - off] : 0;
        __syncthreads();
        sred[tid] += v;
        __syncthreads();
    }
    int run = (tid == 0) ? 0 : sred[tid - 1];
    if (tid == 255) g_total[b] = sred[255];
    for (int i = 0; i < per; i++) {
        const int t = t0 + i;
        if (t < T) {
            g_toffs[t * NBKT + b] = run;
            run += g_thist[t * NBKT + b];
        }
    }
}

// ---------------------------------------------------------------------------
// Base: exclusive scan over 300 bucket totals (+ grand total M).
// ---------------------------------------------------------------------------
__global__ void k_base()
{
    __shared__ int s[NBKT];
    const int tid = threadIdx.x;
    if (tid < NBKT) s[tid] = g_total[tid];
    __syncthreads();
    if (tid == 0) {
        int run = 0;
        for (int b = 0; b < NBKT; b++) { g_base[b] = run; run += s[b]; }
        g_M[0] = run;
    }
}

// ---------------------------------------------------------------------------
// Scatter: stable counting-sort scatter. Warp-private counters; ranks within
// a 32-lane step via match_any (lane order) -> fully deterministic.
// ---------------------------------------------------------------------------
__global__ __launch_bounds__(256)
void k_scatter(int N, int T)
{
    __shared__ int sctr[8][NBKT];
    const int wid = threadIdx.x >> 5, lane = threadIdx.x & 31;
    const int t = blockIdx.x * 8 + wid;
    if (t >= T) return;
    int* ctr = sctr[wid];
    for (int b = lane; b < NBKT; b += 32)
        ctr[b] = g_toffs[t * NBKT + b] + g_base[b];
    __syncwarp();

    const int p0 = t * TS;
    for (int s = 0; s < TS; s += 32) {
        const int idx = p0 + s + lane;
        const unsigned c = (idx < N) ? (unsigned)g_codes[idx] : INVC;
        const unsigned mm = __match_any_sync(0xffffffffu, c);
        const int leader = __ffs(mm) - 1;
        const int rank = __popc(mm & ((1u << lane) - 1u));
        if (c < NBKT) {
            const int bp = ctr[c];                 // broadcast read
            g_sorted[bp + rank] = ((unsigned)idx << 9) | c;
        }
        __syncwarp();
        if (lane == leader && c < NBKT) ctr[c] += __popc(mm);
        __syncwarp();
    }
}

// ---------------------------------------------------------------------------
// K1: register-accumulating gather over the sorted list. Per point: whole
// warp loads one 512B row (1 LDG.128) and adds into float4 registers.
// Interior runs -> exclusive direct SMEM store; boundary runs -> per-warp
// staging slots merged sequentially by warp 0 (deterministic, race-free).
// ---------------------------------------------------------------------------
__global__ __launch_bounds__(256, 1)
void k1_gather(const float* __restrict__ pred)
{
    extern __shared__ float sm[];
    float* acc   = sm;                         // [300][128]
    float* slots = sm + NBKT * D;              // [16][128]
    int*   smeta = (int*)(slots + 16 * D);     // [16]
    const int tid = threadIdx.x, wid = tid >> 5, lane = tid & 31;

    for (int i = tid; i < NBKT * D; i += 256) acc[i] = 0.0f;
    if (tid < 16) smeta[tid] = -1;
    __syncthreads();

    const int M      = g_M[0];
    const int perCTA = (M + GRID1 - 1) / GRID1;
    const int c0     = min(M, blockIdx.x * perCTA);
    const int c1     = min(M, c0 + perCTA);
    const int perW   = (perCTA + 7) / 8;
    const int s0     = min(c1, c0 + wid * perW);
    const int s1     = min(c1, s0 + perW);

    float4 av = make_float4(0.f, 0.f, 0.f, 0.f);
    int cur = -1;
    bool headDone = false;

    for (int p = s0; p < s1; p += 32) {
        const unsigned e = (p + lane < s1) ? g_sorted[p + lane] : 0xFFFFFFFFu;
        #pragma unroll
        for (int g = 0; g < 4; g++) {
            unsigned eg[8];
            float4 v[8];
            #pragma unroll
            for (int k = 0; k < 8; k++) {
                eg[k] = __shfl_sync(0xffffffffu, e, g * 8 + k);
                const unsigned b = eg[k] & 511u;
                const unsigned idx = (b < NBKT) ? (eg[k] >> 9) : 0u;
                v[k] = ((const float4*)(pred + (size_t)idx * D))[lane];
            }
            #pragma unroll
            for (int k = 0; k < 8; k++) {
                const int b = (int)(eg[k] & 511u);
                if (b >= NBKT) continue;             // tail marker (warp-uniform)
                if (b != cur) {
                    if (cur >= 0) {
                        if (!headDone) {             // first run of span: stage
                            ((float4*)(slots + (wid * 2) * D))[lane] = av;
                            if (lane == 0) smeta[wid * 2] = cur;
                            headDone = true;
                        } else {                     // interior run: exclusive
                            ((float4*)(acc + cur * D))[lane] = av;
                        }
                    }
                    av = make_float4(0.f, 0.f, 0.f, 0.f);
                    cur = b;
                }
                av.x += v[k].x; av.y += v[k].y; av.z += v[k].z; av.w += v[k].w;
            }
        }
    }
    if (cur >= 0) {                                  // last run of span: stage
        const int slot = headDone ? (wid * 2 + 1) : (wid * 2);
        ((float4*)(slots + slot * D))[lane] = av;
        if (lane == 0) smeta[slot] = cur;
    }
    __syncthreads();

    if (wid == 0) {                                  // deterministic slot merge
        for (int s = 0; s < 16; s++) {
            const int b = smeta[s];
            if (b >= 0) {
                float4 sv = ((float4*)(slots + s * D))[lane];
                float4 a  = ((float4*)(acc + b * D))[lane];
                a.x += sv.x; a.y += sv.y; a.z += sv.z; a.w += sv.w;
                ((float4*)(acc + b * D))[lane] = a;
            }
        }
    }
    __syncthreads();

    float* out = g_part1 + (size_t)blockIdx.x * (NBKT * D);
    for (int i = tid; i < NBKT * D; i += 256) out[i] = acc[i];
}

// ---------------------------------------------------------------------------
// K2: reduce CTA slabs -> mean -> L2 normalize. grid = NBKT blocks, D threads.
// ---------------------------------------------------------------------------
__global__ void k2_mean_norm()
{
    __shared__ float red[D];
    const int gc = blockIdx.x;
    const int d  = threadIdx.x;
    const float cnt = fmaxf((float)g_total[gc], 1.0f);

    float s = 0.0f;
    for (int k = 0; k < GRID1; k++)
        s += g_part1[(size_t)k * (NBKT * D) + gc * D + d];
    const float mean = s / cnt;

    red[d] = mean * mean; __syncthreads();
    for (int s2 = 64; s2 > 0; s2 >>= 1) { if (d < s2) red[d] += red[d + s2]; __syncthreads(); }
    const float inv = rsqrtf(red[0]);

    g_ab[gc * D + d] = mean * inv;
}

// ---------------------------------------------------------------------------
// K3: block i computes logits row i AND column i (two 256-thread groups),
// then both logsumexps. grid = C blocks, 512 threads.
// ---------------------------------------------------------------------------
__global__ __launch_bounds__(512)
void k3_lse()
{
    extern __shared__ float s3[];
    float* aT  = s3;                 // [D][152]
    float* bT  = aT + D * 152;       // [D][152]
    float* ai  = bT + D * 152;       // [D]
    float* bi  = ai + D;             // [D]
    float* red = bi + D;             // [2][256]
    __shared__ float diag_s, lse_s[2];

    const int i = blockIdx.x, tid = threadIdx.x;
    const int g2 = tid >> 8;
    const int j  = tid & 255;

    for (int idx = tid; idx < C * D; idx += 512) {
        const int c = idx >> 7, d = idx & 127;
        aT[d * 152 + c] = g_ab[idx];
        bT[d * 152 + c] = g_ab[C * D + idx];
    }
    if (tid < D)            ai[tid] = g_ab[i * D + tid];
    else if (tid < 2 * D)   bi[tid - D] = g_ab[C * D + i * D + (tid - D)];
    __syncthreads();

    float x = -1e30f;
    if (j < C) {
        const float* vec = g2 ? bi : ai;
        const float* mat = g2 ? aT : bT;
        float xs = 0.0f;
        #pragma unroll 8
        for (int k = 0; k < D; k++) xs += vec[k] * mat[k * 152 + j];
        x = xs * INV_TEMP;
        if (g2 == 0 && j == i) diag_s = x;
    }

    red[tid] = x; __syncthreads();
    for (int s = 128; s > 0; s >>= 1) {
        if (j < s) red[tid] = fmaxf(red[tid], red[tid + s]);
        __syncthreads();
    }
    const float mx = red[g2 << 8]; __syncthreads();
    red[tid] = (j < C) ? expf(x - mx) : 0.0f; __syncthreads();
    for (int s = 128; s > 0; s >>= 1) {
        if (j < s) red[tid] += red[tid + s];
        __syncthreads();
    }
    if (j == 0) lse_s[g2] = mx + logf(red[g2 << 8]);
    __syncthreads();

    if (tid == 0) g_contrib[i] = lse_s[0] + lse_s[1] - 2.0f * diag_s;
}

// ---------------------------------------------------------------------------
// K4: final scalar.
// ---------------------------------------------------------------------------
__global__ void k4_final(float* __restrict__ out)
{
    __shared__ float red[256];
    const int tid = threadIdx.x;
    red[tid] = (tid < C) ? g_contrib[tid] : 0.0f; __syncthreads();
    for (int s = 128; s > 0; s >>= 1) { if (tid < s) red[tid] += red[tid + s]; __syncthreads(); }
    if (tid == 0) out[0] = red[0] * (1.0f / (2.0f * C));
}

// ---------------------------------------------------------------------------
extern "C" void kernel_launch(void* const* d_in, const int* in_sizes, int n_in,
                              void* d_out, int out_size)
{
    const float* pred = (const float*)d_in[0];
    // d_in[1] = target (unused by the loss math)
    const int* mask = (const int*)d_in[2];
    const int* seg  = (const int*)d_in[3];
    const int* grp  = (const int*)d_in[4];
    const int N = in_sizes[2];

    const int T   = (N + TS - 1) / TS;        // sort tiles
    const int nbl = (T + 7) / 8;              // 8 warp-tiles per block

    const size_t smem1 = (NBKT * D + 16 * D) * sizeof(float) + 16 * sizeof(int);
    cudaFuncSetAttribute(k1_gather, cudaFuncAttributeMaxDynamicSharedMemorySize, (int)smem1);
    const size_t smem3 = (2 * D * 152 + 2 * D + 512) * sizeof(float);
    cudaFuncSetAttribute(k3_lse, cudaFuncAttributeMaxDynamicSharedMemorySize, (int)smem3);

    k0_encode<<<nbl, 256>>>(mask, seg, grp, N, T);
    k_scanA<<<NBKT, 256>>>(T);
    k_base<<<1, 512>>>();
    k_scatter<<<nbl, 256>>>(N, T);
    k1_gather<<<GRID1, 256, smem1>>>(pred);
    k2_mean_norm<<<NBKT, D>>>();
    k3_lse<<<C, 512, smem3>>>();
    k4_final<<<1, 256>>>((float*)d_out);
}